// round 1
// baseline (speedup 1.0000x reference)
#include <cuda_runtime.h>
#include <cuda_bf16.h>

#define N_NODES 50000
#define N_EDGES 600000
#define HID     128
#define N_GRAPHS 512
#define BN_EPS  1e-5f

// ---------------- scratch (static device allocations; no cudaMalloc) ----------------
__device__ float g_h0[N_NODES * HID];
__device__ float g_t1[N_NODES * HID];
__device__ float g_h1[N_NODES * HID];
__device__ float g_hbn[N_NODES * HID];
__device__ float g_neigh[N_NODES * HID];

__device__ int   g_deg[N_NODES];
__device__ int   g_off[N_NODES + 1];
__device__ int   g_cur[N_NODES];
__device__ int   g_csr[N_EDGES];
__device__ float g_invdeg[N_NODES];

__device__ float g_bnsum[HID];
__device__ float g_bnsq[HID];
__device__ float g_scale[HID];
__device__ float g_shift[HID];

// ---------------- small helpers ----------------
__device__ __forceinline__ unsigned long long pack_dup(float x) {
    unsigned long long d;
    asm("mov.b64 %0,{%1,%1};" : "=l"(d) : "f"(x));
    return d;
}

// ---------------- setup kernels ----------------
__global__ void zero_init_kernel() {
    int i = blockIdx.x * blockDim.x + threadIdx.x;
    if (i < N_NODES) g_deg[i] = 0;
    if (i < HID) { g_bnsum[i] = 0.f; g_bnsq[i] = 0.f; }
}

__global__ void hist_kernel(const int* __restrict__ dst) {
    int e = blockIdx.x * blockDim.x + threadIdx.x;
    if (e < N_EDGES) atomicAdd(&g_deg[dst[e]], 1);
}

// single-block exclusive scan over degrees -> offsets, cursor, inv_deg
__global__ void scan_kernel() {
    __shared__ int sh[1024];
    const int CH = (N_NODES + 1023) / 1024;  // 49
    int t = threadIdx.x;
    int base = t * CH;
    int tsum = 0;
    for (int i = 0; i < CH; i++) {
        int idx = base + i;
        if (idx < N_NODES) tsum += g_deg[idx];
    }
    sh[t] = tsum;
    __syncthreads();
    for (int off = 1; off < 1024; off <<= 1) {
        int v = (t >= off) ? sh[t - off] : 0;
        __syncthreads();
        sh[t] += v;
        __syncthreads();
    }
    int run = sh[t] - tsum;  // exclusive prefix
    for (int i = 0; i < CH; i++) {
        int idx = base + i;
        if (idx < N_NODES) {
            int d = g_deg[idx];
            g_off[idx] = run;
            g_cur[idx] = run;
            g_invdeg[idx] = 1.0f / (float)max(d, 1);
            run += d;
        }
    }
    if (t == 1023) g_off[N_NODES] = sh[1023];
}

__global__ void scatter_kernel(const int* __restrict__ src, const int* __restrict__ dst) {
    int e = blockIdx.x * blockDim.x + threadIdx.x;
    if (e < N_EDGES) {
        int d = dst[e];
        int p = atomicAdd(&g_cur[d], 1);
        g_csr[p] = src[e];
    }
}

// ---------------- aggregation kernels (warp per node) ----------------
__global__ void gin_agg_kernel(const float* __restrict__ x) {
    int w = (blockIdx.x * blockDim.x + threadIdx.x) >> 5;
    int lane = threadIdx.x & 31;
    if (w >= N_NODES) return;
    const float4* x4 = (const float4*)x;
    float4 acc = __ldg(&x4[w * 32 + lane]);  // self (GIN eps=0: x + sum)
    int e = g_off[w], end = g_off[w + 1];
    for (; e + 4 <= end; e += 4) {
        int s0 = g_csr[e + 0], s1 = g_csr[e + 1], s2 = g_csr[e + 2], s3 = g_csr[e + 3];
        float4 v0 = __ldg(&x4[s0 * 32 + lane]);
        float4 v1 = __ldg(&x4[s1 * 32 + lane]);
        float4 v2 = __ldg(&x4[s2 * 32 + lane]);
        float4 v3 = __ldg(&x4[s3 * 32 + lane]);
        acc.x += v0.x + v1.x + v2.x + v3.x;
        acc.y += v0.y + v1.y + v2.y + v3.y;
        acc.z += v0.z + v1.z + v2.z + v3.z;
        acc.w += v0.w + v1.w + v2.w + v3.w;
    }
    for (; e < end; e++) {
        int s0 = g_csr[e];
        float4 v0 = __ldg(&x4[s0 * 32 + lane]);
        acc.x += v0.x; acc.y += v0.y; acc.z += v0.z; acc.w += v0.w;
    }
    ((float4*)g_h0)[w * 32 + lane] = acc;
}

__device__ __forceinline__ float4 bn_relu4(float4 h, float4 sc, float4 sh) {
    float4 r;
    r.x = fmaxf(fmaf(h.x, sc.x, sh.x), 0.f);
    r.y = fmaxf(fmaf(h.y, sc.y, sh.y), 0.f);
    r.z = fmaxf(fmaf(h.z, sc.z, sh.z), 0.f);
    r.w = fmaxf(fmaf(h.w, sc.w, sh.w), 0.f);
    return r;
}

// applies BN(scale/shift)+relu on the fly; writes hbn (self, transformed) and
// neigh = inv_deg * sum of transformed neighbor rows
__global__ void sage_agg_kernel(const float* __restrict__ hraw,
                                float* __restrict__ hbn,
                                float* __restrict__ neigh) {
    int w = (blockIdx.x * blockDim.x + threadIdx.x) >> 5;
    int lane = threadIdx.x & 31;
    if (w >= N_NODES) return;
    float4 sc = *(const float4*)&g_scale[lane * 4];
    float4 sh = *(const float4*)&g_shift[lane * 4];
    const float4* h4 = (const float4*)hraw;

    float4 self = bn_relu4(__ldg(&h4[w * 32 + lane]), sc, sh);
    ((float4*)hbn)[w * 32 + lane] = self;

    float4 acc = make_float4(0.f, 0.f, 0.f, 0.f);
    int e = g_off[w], end = g_off[w + 1];
    for (; e + 4 <= end; e += 4) {
        int s0 = g_csr[e + 0], s1 = g_csr[e + 1], s2 = g_csr[e + 2], s3 = g_csr[e + 3];
        float4 v0 = bn_relu4(__ldg(&h4[s0 * 32 + lane]), sc, sh);
        float4 v1 = bn_relu4(__ldg(&h4[s1 * 32 + lane]), sc, sh);
        float4 v2 = bn_relu4(__ldg(&h4[s2 * 32 + lane]), sc, sh);
        float4 v3 = bn_relu4(__ldg(&h4[s3 * 32 + lane]), sc, sh);
        acc.x += v0.x + v1.x + v2.x + v3.x;
        acc.y += v0.y + v1.y + v2.y + v3.y;
        acc.z += v0.z + v1.z + v2.z + v3.z;
        acc.w += v0.w + v1.w + v2.w + v3.w;
    }
    for (; e < end; e++) {
        int s0 = g_csr[e];
        float4 v0 = bn_relu4(__ldg(&h4[s0 * 32 + lane]), sc, sh);
        acc.x += v0.x; acc.y += v0.y; acc.z += v0.z; acc.w += v0.w;
    }
    float id = g_invdeg[w];
    acc.x *= id; acc.y *= id; acc.z *= id; acc.w *= id;
    ((float4*)neigh)[w * 32 + lane] = acc;
}

// ---------------- GEMM: out[M,128] = sum_parts A_p[M,128] @ W_p[128,128] + bias ----------------
// 128-row tile per block, 256 threads, thread tile = 16 rows x 4 cols, f32x2 FMA.
#define GBM 128
#define GKC 16
#define APAD 4

__global__ __launch_bounds__(256, 2) void gemm128_kernel(
    const float* __restrict__ A1, const float* __restrict__ W1,
    const float* __restrict__ A2, const float* __restrict__ W2,
    const float* __restrict__ bias, float* __restrict__ out,
    int M, int nparts, int do_relu, int do_stats)
{
    __shared__ __align__(16) float As[GKC][HID + APAD];
    __shared__ __align__(16) float Bs[GKC][HID];
    __shared__ float csum[HID], csq[HID];

    int tid = threadIdx.x;
    int tcol = tid & 31;   // 0..31 -> cols [tcol*4, tcol*4+4)
    int trow = tid >> 5;   // 0..7  -> rows [trow*16, trow*16+16)
    int rowBase = blockIdx.x * GBM;

    unsigned long long acc[8][4];
#pragma unroll
    for (int r = 0; r < 8; r++)
#pragma unroll
        for (int c = 0; c < 4; c++) acc[r][c] = 0ULL;

    if (do_stats && tid < HID) { csum[tid] = 0.f; csq[tid] = 0.f; }

    for (int part = 0; part < nparts; part++) {
        const float* A = part ? A2 : A1;
        const float* W = part ? W2 : W1;
        for (int kc = 0; kc < HID; kc += GKC) {
            __syncthreads();
            // load A chunk [128 rows x 16 k], stored transposed As[k][row]
            {
                int q = tid & 3;     // k quad within chunk
                int r0 = tid >> 2;   // 0..63
#pragma unroll
                for (int ph = 0; ph < 2; ph++) {
                    int row = r0 + ph * 64;
                    int grow = rowBase + row;
                    if (grow >= M) grow = M - 1;
                    float4 v = __ldg((const float4*)&A[grow * HID + kc + q * 4]);
                    As[q * 4 + 0][row] = v.x;
                    As[q * 4 + 1][row] = v.y;
                    As[q * 4 + 2][row] = v.z;
                    As[q * 4 + 3][row] = v.w;
                }
            }
            // load W chunk [16 k x 128 n]
            {
                int c4 = tid & 31;
                int kr = tid >> 5;
#pragma unroll
                for (int ph = 0; ph < 2; ph++) {
                    int k = kr + ph * 8;
                    float4 v = __ldg((const float4*)&W[(kc + k) * HID + c4 * 4]);
                    *(float4*)&Bs[k][c4 * 4] = v;
                }
            }
            __syncthreads();
#pragma unroll
            for (int k = 0; k < GKC; k++) {
                unsigned long long a[8];
                const float* ar = &As[k][trow * 16];
                ulonglong2 t;
                t = *(const ulonglong2*)(ar + 0);  a[0] = t.x; a[1] = t.y;
                t = *(const ulonglong2*)(ar + 4);  a[2] = t.x; a[3] = t.y;
                t = *(const ulonglong2*)(ar + 8);  a[4] = t.x; a[5] = t.y;
                t = *(const ulonglong2*)(ar + 12); a[6] = t.x; a[7] = t.y;
                float4 b4 = *(const float4*)&Bs[k][tcol * 4];
                unsigned long long bb0 = pack_dup(b4.x);
                unsigned long long bb1 = pack_dup(b4.y);
                unsigned long long bb2 = pack_dup(b4.z);
                unsigned long long bb3 = pack_dup(b4.w);
#pragma unroll
                for (int r = 0; r < 8; r++) {
                    asm("fma.rn.f32x2 %0,%1,%2,%0;" : "+l"(acc[r][0]) : "l"(a[r]), "l"(bb0));
                    asm("fma.rn.f32x2 %0,%1,%2,%0;" : "+l"(acc[r][1]) : "l"(a[r]), "l"(bb1));
                    asm("fma.rn.f32x2 %0,%1,%2,%0;" : "+l"(acc[r][2]) : "l"(a[r]), "l"(bb2));
                    asm("fma.rn.f32x2 %0,%1,%2,%0;" : "+l"(acc[r][3]) : "l"(a[r]), "l"(bb3));
                }
            }
        }
    }

    // epilogue: bias (+relu) (+BN stats) + store
    float4 bias4 = __ldg((const float4*)&bias[tcol * 4]);
    float bv[4] = { bias4.x, bias4.y, bias4.z, bias4.w };
    float lsum[4] = {0, 0, 0, 0}, lsq[4] = {0, 0, 0, 0};
#pragma unroll
    for (int r = 0; r < 8; r++) {
        float vlo[4], vhi[4];
#pragma unroll
        for (int c = 0; c < 4; c++) {
            unsigned long long u = acc[r][c];
            vlo[c] = __uint_as_float((unsigned)u) + bv[c];
            vhi[c] = __uint_as_float((unsigned)(u >> 32)) + bv[c];
            if (do_relu) { vlo[c] = fmaxf(vlo[c], 0.f); vhi[c] = fmaxf(vhi[c], 0.f); }
        }
        int row0 = rowBase + trow * 16 + 2 * r;
        if (row0 < M) {
            *(float4*)&out[row0 * HID + tcol * 4] = make_float4(vlo[0], vlo[1], vlo[2], vlo[3]);
            if (do_stats)
#pragma unroll
                for (int c = 0; c < 4; c++) { lsum[c] += vlo[c]; lsq[c] += vlo[c] * vlo[c]; }
        }
        if (row0 + 1 < M) {
            *(float4*)&out[(row0 + 1) * HID + tcol * 4] = make_float4(vhi[0], vhi[1], vhi[2], vhi[3]);
            if (do_stats)
#pragma unroll
                for (int c = 0; c < 4; c++) { lsum[c] += vhi[c]; lsq[c] += vhi[c] * vhi[c]; }
        }
    }
    if (do_stats) {
#pragma unroll
        for (int c = 0; c < 4; c++) {
            atomicAdd(&csum[tcol * 4 + c], lsum[c]);
            atomicAdd(&csq[tcol * 4 + c], lsq[c]);
        }
        __syncthreads();
        if (tid < HID) {
            atomicAdd(&g_bnsum[tid], csum[tid]);
            atomicAdd(&g_bnsq[tid], csq[tid]);
        }
    }
}

// ---------------- BN finalize: scale/shift from accumulated sums ----------------
__global__ void bn_finalize_kernel(const float* __restrict__ gamma, const float* __restrict__ beta) {
    int c = threadIdx.x;
    const float invn = 1.0f / (float)N_NODES;
    float m = g_bnsum[c] * invn;
    float var = g_bnsq[c] * invn - m * m;
    var = fmaxf(var, 0.f);
    float s = gamma[c] * rsqrtf(var + BN_EPS);
    g_scale[c] = s;
    g_shift[c] = beta[c] - m * s;
    g_bnsum[c] = 0.f;
    g_bnsq[c] = 0.f;
}

// ---------------- pooling: batch is sorted, block per graph ----------------
__device__ __forceinline__ int lbound(const int* a, int n, int v) {
    int lo = 0, hi = n;
    while (lo < hi) {
        int mid = (lo + hi) >> 1;
        if (a[mid] < v) lo = mid + 1; else hi = mid;
    }
    return lo;
}

__global__ void pool_kernel(const float* __restrict__ hraw,
                            const int* __restrict__ batch,
                            float* __restrict__ out) {
    int g = blockIdx.x;
    int c = threadIdx.x;
    int start = lbound(batch, N_NODES, g);
    int end = lbound(batch, N_NODES, g + 1);
    int cnt = end - start;
    float sc = g_scale[c], sh = g_shift[c];
    float s = 0.f;
    for (int i = start; i < end; i++) {
        float v = fmaf(hraw[i * HID + c], sc, sh);
        s += fmaxf(v, 0.f);
    }
    out[g * HID + c] = s / fmaxf((float)cnt, 1.f);
}

// ---------------- launch ----------------
extern "C" void kernel_launch(void* const* d_in, const int* in_sizes, int n_in,
                              void* d_out, int out_size) {
    (void)in_sizes; (void)n_in; (void)out_size;
    const float* x       = (const float*)d_in[0];
    const int*   eidx    = (const int*)d_in[1];
    const int*   batch   = (const int*)d_in[2];
    const float* gin_w1  = (const float*)d_in[3];
    const float* gin_b1  = (const float*)d_in[4];
    const float* gin_w2  = (const float*)d_in[5];
    const float* gin_b2  = (const float*)d_in[6];
    const float* sage_wl = (const float*)d_in[7];
    const float* sage_bl = (const float*)d_in[8];
    const float* sage_wr = (const float*)d_in[9];
    const float* bn_g    = (const float*)d_in[10];
    const float* bn_b    = (const float*)d_in[11];
    float* out = (float*)d_out;

    const int* src = eidx;
    const int* dst = eidx + N_EDGES;

    float *p_h0, *p_t1, *p_h1, *p_hbn, *p_ng;
    cudaGetSymbolAddress((void**)&p_h0, g_h0);
    cudaGetSymbolAddress((void**)&p_t1, g_t1);
    cudaGetSymbolAddress((void**)&p_h1, g_h1);
    cudaGetSymbolAddress((void**)&p_hbn, g_hbn);
    cudaGetSymbolAddress((void**)&p_ng, g_neigh);

    const int M = N_NODES;
    const int gemmGrid = (M + GBM - 1) / GBM;   // 391
    const int aggGrid = (N_NODES * 32 + 255) / 256;  // warp per node
    const int edgeGrid = (N_EDGES + 255) / 256;

    // CSR build (degrees reused for all layers)
    zero_init_kernel<<<(N_NODES + 255) / 256, 256>>>();
    hist_kernel<<<edgeGrid, 256>>>(dst);
    scan_kernel<<<1, 1024>>>();
    scatter_kernel<<<edgeGrid, 256>>>(src, dst);

    // Layer 0: GIN
    gin_agg_kernel<<<aggGrid, 256>>>(x);
    gemm128_kernel<<<gemmGrid, 256>>>(p_h0, gin_w1, p_h0, gin_w1, gin_b1, p_t1, M, 1, 1, 0);
    gemm128_kernel<<<gemmGrid, 256>>>(p_t1, gin_w2, p_t1, gin_w2, gin_b2, p_h1, M, 1, 0, 1);
    bn_finalize_kernel<<<1, HID>>>(bn_g + 0 * HID, bn_b + 0 * HID);

    // SAGE layer 0
    sage_agg_kernel<<<aggGrid, 256>>>(p_h1, p_hbn, p_ng);
    gemm128_kernel<<<gemmGrid, 256>>>(p_ng, sage_wl, p_hbn, sage_wr, sage_bl, p_h0, M, 2, 0, 1);
    bn_finalize_kernel<<<1, HID>>>(bn_g + 1 * HID, bn_b + 1 * HID);

    // SAGE layer 1
    sage_agg_kernel<<<aggGrid, 256>>>(p_h0, p_hbn, p_ng);
    gemm128_kernel<<<gemmGrid, 256>>>(p_ng, sage_wl + HID * HID, p_hbn, sage_wr + HID * HID,
                                      sage_bl + HID, p_t1, M, 2, 0, 1);
    bn_finalize_kernel<<<1, HID>>>(bn_g + 2 * HID, bn_b + 2 * HID);

    // global mean pool (batch sorted)
    pool_kernel<<<N_GRAPHS, HID>>>(p_t1, batch, out);
}